// round 16
// baseline (speedup 1.0000x reference)
#include <cuda_runtime.h>
#include <cuda_fp16.h>
#include <cstdint>

#define N_NODES 50000
#define N_EDGES 800000
#define C 128
#define NCLS 40
#define NB_SCAN ((N_NODES + 255) / 256)        // 196
#define PREP_BLOCKS ((N_NODES * C / 4 + 255) / 256)  // 6250
#define EDGE4_BLOCKS ((N_EDGES / 4 + 255) / 256)     // 782
#define EDGE2_BLOCKS ((N_EDGES / 2 + 255) / 256)     // 1563

// ======================= scratch (no allocation allowed) ====================
__device__ __align__(256) float g_deg_inv[N_NODES];
__device__ __align__(256) int   g_deg[N_NODES];    // zero at load; csrfill re-zeroes
__device__ __align__(256) int   g_off[N_NODES + 1];
__device__ __align__(256) int   g_rank[N_EDGES];   // per-edge rank within its dst segment
__device__ __align__(256) int   g_csr_src[N_EDGES];
__device__ __align__(256) int   g_bsum[NB_SCAN];
__device__ __align__(256) int   g_bflag[NB_SCAN];  // zero at load; csrfill re-zeroes
// fp16 activation images
__device__ __align__(256) __half g_x_f16[N_NODES * C];
__device__ __align__(256) __half g_h1_f16[N_NODES * C];
__device__ __align__(256) __half g_agg_f16[N_NODES * C];
// Weight images: plain fp16
__device__ __align__(256) __half g_B1[256 * 128];
__device__ __align__(256) __half g_B2[256 * 128];
__device__ __align__(256) __half g_Wc[128 * 64];
__device__ int g_idx64;

// ======================= helpers =======================
__device__ __forceinline__ uint32_t smem_u32(const void* p) {
    uint32_t a;
    asm("{ .reg .u64 t; cvta.to.shared.u64 t, %1; cvt.u32.u64 %0, t; }"
        : "=r"(a) : "l"(p));
    return a;
}
__device__ __forceinline__ void ldsm_x4(uint32_t& r0, uint32_t& r1,
                                        uint32_t& r2, uint32_t& r3, uint32_t addr) {
    asm volatile("ldmatrix.sync.aligned.m8n8.x4.shared.b16 {%0,%1,%2,%3}, [%4];"
                 : "=r"(r0), "=r"(r1), "=r"(r2), "=r"(r3) : "r"(addr));
}
__device__ __forceinline__ void ldsm_x4_t(uint32_t& r0, uint32_t& r1,
                                          uint32_t& r2, uint32_t& r3, uint32_t addr) {
    asm volatile("ldmatrix.sync.aligned.m8n8.x4.trans.shared.b16 {%0,%1,%2,%3}, [%4];"
                 : "=r"(r0), "=r"(r1), "=r"(r2), "=r"(r3) : "r"(addr));
}
__device__ __forceinline__ void mma_f16(float* c, const uint32_t* a, const uint32_t* b) {
    asm volatile(
        "mma.sync.aligned.m16n8k16.row.col.f32.f16.f16.f32 "
        "{%0,%1,%2,%3}, {%4,%5,%6,%7}, {%8,%9}, {%0,%1,%2,%3};"
        : "+f"(c[0]), "+f"(c[1]), "+f"(c[2]), "+f"(c[3])
        : "r"(a[0]), "r"(a[1]), "r"(a[2]), "r"(a[3]), "r"(b[0]), "r"(b[1]));
}
__device__ __forceinline__ int block_incl_scan(int v, int* wsum /*[8]*/) {
    int lane = threadIdx.x & 31, w = threadIdx.x >> 5;
#pragma unroll
    for (int off = 1; off < 32; off <<= 1) {
        int u = __shfl_up_sync(0xffffffffu, v, off);
        if (lane >= off) v += u;
    }
    if (lane == 31) wsum[w] = v;
    __syncthreads();
    if (w == 0) {
        int s = (lane < 8) ? wsum[lane] : 0;
#pragma unroll
        for (int off = 1; off < 8; off <<= 1) {
            int u = __shfl_up_sync(0xffffffffu, s, off);
            if (lane >= off) s += u;
        }
        if (lane < 8) wsum[lane] = s;
    }
    __syncthreads();
    if (w > 0) v += wsum[w - 1];
    return v;
}

// ====== fused prep + degree histogram (independent work, one grid) ==========
__global__ void __launch_bounds__(256)
prep_deg_kernel(const unsigned int* __restrict__ ei,
                const float* __restrict__ x,
                const float* __restrict__ Wl1, const float* __restrict__ Wr1,
                const float* __restrict__ Wl2, const float* __restrict__ Wr2,
                const float* __restrict__ Wc) {
    const int b = blockIdx.x;
    const int t = threadIdx.x;
    if (b < PREP_BLOCKS) {
        int i = b * 256 + t;
        if (i == 0) {
            int zeros = 0;
            for (int j = 1; j < 128; j += 2) zeros += (ei[j] == 0u);
            g_idx64 = (zeros >= 32) ? 1 : 0;
        }
        if (i < 2 * 256 * 128) {
            int layer = i >> 15;
            int rem = i & 32767;
            int k = rem >> 7;
            int n = rem & 127;
            const float* W = (layer == 0) ? ((k < 128) ? Wl1 : Wr1) : ((k < 128) ? Wl2 : Wr2);
            float v = W[(k & 127) * 128 + n];
            (layer ? g_B2 : g_B1)[k * 128 + n] = __float2half_rn(v);
        } else if (i < 2 * 256 * 128 + 128 * 64) {
            int rem = i - 2 * 256 * 128;
            int k = rem >> 6;
            int n = rem & 63;
            float v = (n < NCLS) ? Wc[k * NCLS + n] : 0.f;
            g_Wc[k * 64 + n] = __float2half_rn(v);
        }
        if (i < N_NODES * C / 4) {
            float4 v = ((const float4*)x)[i];
            __half2 f0 = __floats2half2_rn(v.x, v.y);
            __half2 f1 = __floats2half2_rn(v.z, v.w);
            uint2 f;
            f.x = *(uint32_t*)&f0;
            f.y = *(uint32_t*)&f1;
            ((uint2*)g_x_f16)[i] = f;
        }
    } else {
        // ---- degree histogram + rank recording (self-detects index width) ----
        __shared__ int s64;
        if (t < 32) {
            unsigned z = (ei[2 * t + 1] == 0u) ? 1u : 0u;
            unsigned bal = __ballot_sync(0xffffffffu, z);
            if (t == 0) s64 = (__popc(bal) >= 16) ? 1 : 0;
        }
        __syncthreads();
        const int is64 = s64;
        int i = (b - PREP_BLOCKS) * 256 + t;
        if (i * 4 >= N_EDGES) return;
        int d0, d1, d2, d3;
        if (is64) {
            const longlong2* p = (const longlong2*)((const long long*)ei + N_EDGES);
            longlong2 v0 = p[2 * i], v1 = p[2 * i + 1];
            d0 = (int)v0.x; d1 = (int)v0.y; d2 = (int)v1.x; d3 = (int)v1.y;
        } else {
            int4 v = ((const int4*)((const int*)ei + N_EDGES))[i];
            d0 = v.x; d1 = v.y; d2 = v.z; d3 = v.w;
        }
        int4 r;
        r.x = atomicAdd(&g_deg[d0], 1);
        r.y = atomicAdd(&g_deg[d1], 1);
        r.z = atomicAdd(&g_deg[d2], 1);
        r.w = atomicAdd(&g_deg[d3], 1);
        ((int4*)g_rank)[i] = r;
    }
}

// ---- single-kernel decoupled-lookback scan over g_deg ----
// 196 blocks, all resident in wave 1 -> spin on predecessor flags is safe.
__global__ void __launch_bounds__(256) scan_all_kernel() {
    __shared__ int ws[8];
    __shared__ int blockTotal;
    __shared__ int pre;
    const int t = threadIdx.x, b = blockIdx.x;
    int i = b * 256 + t;
    int d = (i < N_NODES) ? g_deg[i] : 0;
    int inc = block_incl_scan(d, ws);
    if (t == 255) blockTotal = inc;
    if (t == 0) pre = 0;
    __syncthreads();
    if (t == 0) {
        g_bsum[b] = blockTotal;
        __threadfence();
        atomicExch(&g_bflag[b], 1);
    }
    // lookback: sum aggregates of all predecessor blocks
    for (int j = t; j < b; j += 256) {
        while (atomicAdd(&g_bflag[j], 0) == 0) {}
        atomicAdd(&pre, atomicAdd(&g_bsum[j], 0));
    }
    __syncthreads();
    if (i < N_NODES) {
        int o = pre + inc - d;
        g_off[i] = o;
        g_deg_inv[i] = (d > 0) ? (1.0f / (float)d) : 0.0f;
    }
    if (b == 0 && t == 0) g_off[N_NODES] = N_EDGES;
}

// CSR fill, 2 edges/thread (round-15 lesson: scatter is latency x warp-count
// bound; double the warps). NO atomics: pos = off[dst] + rank[e].
// Re-zeroes g_deg and g_bflag for the NEXT call.
__global__ void csrfill_kernel(const void* __restrict__ ei) {
    int i = blockIdx.x * blockDim.x + threadIdx.x;
    if (i < N_NODES) g_deg[i] = 0;
    if (i < NB_SCAN) g_bflag[i] = 0;
    if (i * 2 >= N_EDGES) return;
    int s0, s1, d0, d1;
    if (g_idx64) {
        longlong2 sv = ((const longlong2*)(const long long*)ei)[i];
        longlong2 dv = ((const longlong2*)((const long long*)ei + N_EDGES))[i];
        s0 = (int)sv.x; s1 = (int)sv.y; d0 = (int)dv.x; d1 = (int)dv.y;
    } else {
        int2 sv = ((const int2*)(const int*)ei)[i];
        int2 dv = ((const int2*)((const int*)ei + N_EDGES))[i];
        s0 = sv.x; s1 = sv.y; d0 = dv.x; d1 = dv.y;
    }
    int2 r = ((const int2*)g_rank)[i];
    g_csr_src[__ldg(&g_off[d0]) + r.x] = s0;
    g_csr_src[__ldg(&g_off[d1]) + r.y] = s1;
}

// ======================= CSR gather-mean (fp16 in, fp16 out) =================
// one warp per node, 4-wide MLP (rounds 10/13: fixed design point)
__global__ void __launch_bounds__(256)
gather_kernel(const __half* __restrict__ feat, __half* __restrict__ agg) {
    int node = (blockIdx.x * blockDim.x + threadIdx.x) >> 5;
    int lane = threadIdx.x & 31;
    if (node >= N_NODES) return;
    int e = g_off[node];
    const int end = g_off[node + 1];
    float4 acc = make_float4(0.f, 0.f, 0.f, 0.f);
#define ACC_H(v) do { \
        __half2 p0 = *(__half2*)&(v).x, p1 = *(__half2*)&(v).y; \
        float2 f0 = __half22float2(p0), f1 = __half22float2(p1); \
        acc.x += f0.x; acc.y += f0.y; acc.z += f1.x; acc.w += f1.y; } while (0)
    for (; e + 4 <= end; e += 4) {
        int i0 = __ldg(&g_csr_src[e]);
        int i1 = __ldg(&g_csr_src[e + 1]);
        int i2 = __ldg(&g_csr_src[e + 2]);
        int i3 = __ldg(&g_csr_src[e + 3]);
        uint2 v0 = *(const uint2*)(feat + (size_t)i0 * C + lane * 4);
        uint2 v1 = *(const uint2*)(feat + (size_t)i1 * C + lane * 4);
        uint2 v2 = *(const uint2*)(feat + (size_t)i2 * C + lane * 4);
        uint2 v3 = *(const uint2*)(feat + (size_t)i3 * C + lane * 4);
        ACC_H(v0); ACC_H(v1); ACC_H(v2); ACC_H(v3);
    }
    for (; e < end; ++e) {
        int s = __ldg(&g_csr_src[e]);
        uint2 v = *(const uint2*)(feat + (size_t)s * C + lane * 4);
        ACC_H(v);
    }
#undef ACC_H
    float s = g_deg_inv[node];
    __half2 o0 = __floats2half2_rn(acc.x * s, acc.y * s);
    __half2 o1 = __floats2half2_rn(acc.z * s, acc.w * s);
    uint2 o;
    o.x = *(uint32_t*)&o0;
    o.y = *(uint32_t*)&o1;
    *(uint2*)(agg + (size_t)node * C + lane * 4) = o;
}

// ======================= HMMA SAGE GEMM (plain fp16) ========================
#define A_STRIDE 72
#define B_STRIDE 136
#define SM_A0 0
#define SM_A1 (128 * A_STRIDE * 2)            // 18432
#define SM_B  (2 * 128 * A_STRIDE * 2)        // 36864
#define SM_TOTAL (2 * 128 * A_STRIDE * 2 + 64 * B_STRIDE * 2)  // 54272 B

template <bool FUSE_CLS>
__global__ void __launch_bounds__(256)
sage_gemm_mma(const __half* __restrict__ agg, const __half* __restrict__ xin,
              const __half* __restrict__ B, const float* __restrict__ bias,
              __half* __restrict__ outf16,
              const float* __restrict__ bc, float* __restrict__ clsout) {
    extern __shared__ unsigned char smem[];
    const uint32_t sbase = smem_u32(smem);
    const int t = threadIdx.x;
    const int wid = t >> 5, lane = t & 31;
    const int warp_m = wid >> 2;
    const int warp_n = wid & 3;
    const int rowBase = blockIdx.x * 128;

    float acc[4][4][4];
#pragma unroll
    for (int i = 0; i < 4; i++)
#pragma unroll
        for (int j = 0; j < 4; j++)
#pragma unroll
            for (int r = 0; r < 4; r++) acc[i][j][r] = 0.f;

    const int a_row = warp_m * 64 + (lane & 15);
    const int a_col = (lane >> 4) * 8;
    const int b_row = (lane & 7) + (lane & 8);
    const int b_col = warp_n * 32 + (lane >> 4) * 8;

    for (int chunk = 0; chunk < 4; ++chunk) {
        const int k0 = chunk * 64;
        const bool isAgg = (chunk < 2);
        const __half* src = isAgg ? agg : xin;
        const int koff = isAgg ? k0 : (k0 - 128);

        // A fill: 128 rows x 64 k fp16 = 1024 uint4
#pragma unroll
        for (int it = 0; it < 4; ++it) {
            int idx = it * 256 + t;
            int row = idx >> 3;
            int q = idx & 7;
            int gm = rowBase + row;
            uint4 v = make_uint4(0u, 0u, 0u, 0u);
            if (gm < N_NODES) v = *(const uint4*)(src + (size_t)gm * C + koff + q * 8);
            uint32_t off = SM_A0 + (uint32_t)(row * A_STRIDE + q * 8) * 2;
            *(uint4*)(smem + off) = v;
        }
        // B fill: 64 k-rows x 128 n = 1024 uint4
#pragma unroll
        for (int it = 0; it < 4; ++it) {
            int idx = it * 256 + t;
            int r = idx >> 4;
            int c8 = (idx & 15) * 8;
            uint4 v = *(const uint4*)(B + (size_t)(k0 + r) * 128 + c8);
            uint32_t off = SM_B + (uint32_t)(r * B_STRIDE + c8) * 2;
            *(uint4*)(smem + off) = v;
        }
        __syncthreads();

#pragma unroll
        for (int ks = 0; ks < 4; ++ks) {
            const int kk = ks * 16;
            uint32_t a[4][4], bh[4][2];
#pragma unroll
            for (int i = 0; i < 4; ++i) {
                uint32_t addr = sbase + SM_A0 +
                    (uint32_t)((a_row + i * 16) * A_STRIDE + kk + a_col) * 2;
                ldsm_x4(a[i][0], a[i][1], a[i][2], a[i][3], addr);
            }
#pragma unroll
            for (int jj = 0; jj < 2; ++jj) {
                uint32_t addr = sbase + SM_B +
                    (uint32_t)((kk + b_row) * B_STRIDE + b_col + jj * 16) * 2;
                ldsm_x4_t(bh[jj * 2][0], bh[jj * 2][1], bh[jj * 2 + 1][0], bh[jj * 2 + 1][1], addr);
            }
#pragma unroll
            for (int i = 0; i < 4; ++i)
#pragma unroll
                for (int j = 0; j < 4; ++j)
                    mma_f16(acc[i][j], a[i], bh[j]);
        }
        __syncthreads();
    }

    const int er = lane >> 2;
    const int ec = (lane & 3) * 2;

    if (!FUSE_CLS) {
        // ---- layer-1 epilogue: bias + relu -> global fp16 ----
#pragma unroll
        for (int i = 0; i < 4; ++i) {
            int gm0 = rowBase + warp_m * 64 + i * 16 + er;
#pragma unroll
            for (int j = 0; j < 4; ++j) {
                int col = warp_n * 32 + j * 8 + ec;
                float b0 = bias[col], b1 = bias[col + 1];
#pragma unroll
                for (int half = 0; half < 2; ++half) {
                    int gm = gm0 + half * 8;
                    if (gm < N_NODES) {
                        float ox = fmaxf(acc[i][j][half * 2 + 0] + b0, 0.f);
                        float oy = fmaxf(acc[i][j][half * 2 + 1] + b1, 0.f);
                        __half2 o2 = __floats2half2_rn(ox, oy);
                        *(uint32_t*)(outf16 + (size_t)gm * C + col) = *(uint32_t*)&o2;
                    }
                }
            }
        }
        return;
    }

    // ---- layer-2 epilogue: bias + relu -> smem h2 tile (A0: 0-63, A1: 64-127)
#pragma unroll
    for (int i = 0; i < 4; ++i) {
        int row0 = warp_m * 64 + i * 16 + er;
#pragma unroll
        for (int j = 0; j < 4; ++j) {
            int col = warp_n * 32 + j * 8 + ec;
            float b0 = bias[col], b1 = bias[col + 1];
            uint32_t region = (col >= 64) ? SM_A1 : SM_A0;
            int colIn = col & 63;
#pragma unroll
            for (int half = 0; half < 2; ++half) {
                int row = row0 + half * 8;
                float ox = fmaxf(acc[i][j][half * 2 + 0] + b0, 0.f);
                float oy = fmaxf(acc[i][j][half * 2 + 1] + b1, 0.f);
                __half2 o2 = __floats2half2_rn(ox, oy);
                *(uint32_t*)(smem + region + (uint32_t)(row * A_STRIDE + colIn) * 2) =
                    *(uint32_t*)&o2;
            }
        }
    }
    __syncthreads();

    // ---- in-CTA classifier: logits = h2_tile @ Wc + bc ----
    float acc2[4][2][4];
#pragma unroll
    for (int i = 0; i < 4; i++)
#pragma unroll
        for (int j = 0; j < 2; j++)
#pragma unroll
            for (int r = 0; r < 4; r++) acc2[i][j][r] = 0.f;

    const int cb_col = warp_n * 16 + (lane >> 4) * 8;

    for (int chunk = 0; chunk < 2; ++chunk) {
        const int k0 = chunk * 64;
        // B fill: Wc 64 k-rows x 64 n = 512 uint4
#pragma unroll
        for (int it = 0; it < 2; ++it) {
            int idx = it * 256 + t;
            int r = idx >> 3;
            int c8 = (idx & 7) * 8;
            uint4 v = *(const uint4*)(g_Wc + (size_t)(k0 + r) * 64 + c8);
            uint32_t off = SM_B + (uint32_t)(r * B_STRIDE + c8) * 2;
            *(uint4*)(smem + off) = v;
        }
        __syncthreads();

        const uint32_t aRegion = chunk ? SM_A1 : SM_A0;
#pragma unroll
        for (int ks = 0; ks < 4; ++ks) {
            const int kk = ks * 16;
            uint32_t a[4][4], bh[2][2];
#pragma unroll
            for (int i = 0; i < 4; ++i) {
                uint32_t addr = sbase + aRegion +
                    (uint32_t)((a_row + i * 16) * A_STRIDE + kk + a_col) * 2;
                ldsm_x4(a[i][0], a[i][1], a[i][2], a[i][3], addr);
            }
            {
                uint32_t addr = sbase + SM_B +
                    (uint32_t)((kk + b_row) * B_STRIDE + cb_col) * 2;
                ldsm_x4_t(bh[0][0], bh[0][1], bh[1][0], bh[1][1], addr);
            }
#pragma unroll
            for (int i = 0; i < 4; ++i)
#pragma unroll
                for (int j = 0; j < 2; ++j)
                    mma_f16(acc2[i][j], a[i], bh[j]);
        }
        __syncthreads();
    }

#pragma unroll
    for (int i = 0; i < 4; ++i) {
        int gm0 = rowBase + warp_m * 64 + i * 16 + er;
#pragma unroll
        for (int j = 0; j < 2; ++j) {
            int col = warp_n * 16 + j * 8 + ec;
            if (col >= NCLS) continue;
            float b0 = bc[col], b1 = bc[col + 1];
#pragma unroll
            for (int half = 0; half < 2; ++half) {
                int gm = gm0 + half * 8;
                if (gm < N_NODES) {
                    float2 o;
                    o.x = acc2[i][j][half * 2 + 0] + b0;
                    o.y = acc2[i][j][half * 2 + 1] + b1;
                    *(float2*)(clsout + (size_t)gm * NCLS + col) = o;
                }
            }
        }
    }
}

// ======================= launch =======================
extern "C" void kernel_launch(void* const* d_in, const int* in_sizes, int n_in,
                              void* d_out, int out_size) {
    (void)in_sizes; (void)n_in; (void)out_size;
    const float* x   = (const float*)d_in[0];
    const void*  ei  = d_in[1];
    const float* Wl1 = (const float*)d_in[2];
    const float* Wr1 = (const float*)d_in[3];
    const float* b1  = (const float*)d_in[4];
    const float* Wl2 = (const float*)d_in[5];
    const float* Wr2 = (const float*)d_in[6];
    const float* b2  = (const float*)d_in[7];
    const float* Wc  = (const float*)d_in[8];
    const float* bc  = (const float*)d_in[9];
    float* out = (float*)d_out;

    __half *xf16, *h1f16, *aggf16;
    cudaGetSymbolAddress((void**)&xf16, g_x_f16);
    cudaGetSymbolAddress((void**)&h1f16, g_h1_f16);
    cudaGetSymbolAddress((void**)&aggf16, g_agg_f16);
    __half *b1p, *b2p;
    cudaGetSymbolAddress((void**)&b1p, g_B1);
    cudaGetSymbolAddress((void**)&b2p, g_B2);

    cudaFuncSetAttribute(sage_gemm_mma<false>, cudaFuncAttributeMaxDynamicSharedMemorySize, SM_TOTAL);
    cudaFuncSetAttribute(sage_gemm_mma<true>, cudaFuncAttributeMaxDynamicSharedMemorySize, SM_TOTAL);

    const int nBlocks = (N_NODES + 127) / 128;            // 391
    const int gatherBlocks = (N_NODES * 32 + 255) / 256;  // 6250

    // fused prep + degree histogram (records per-edge ranks for atomic-free fill)
    prep_deg_kernel<<<PREP_BLOCKS + EDGE4_BLOCKS, 256>>>(
        (const unsigned int*)ei, x, Wl1, Wr1, Wl2, Wr2, Wc);

    // CSR build: single-kernel decoupled-lookback scan, then atomic-free fill
    scan_all_kernel<<<NB_SCAN, 256>>>();
    csrfill_kernel<<<EDGE2_BLOCKS, 256>>>(ei);

    // layer 1
    gather_kernel<<<gatherBlocks, 256>>>(xf16, aggf16);
    sage_gemm_mma<false><<<nBlocks, 256, SM_TOTAL>>>(aggf16, xf16, b1p, b1,
                                                     h1f16, (const float*)0, (float*)0);

    // layer 2 + fused classifier
    gather_kernel<<<gatherBlocks, 256>>>(h1f16, aggf16);
    sage_gemm_mma<true><<<nBlocks, 256, SM_TOTAL>>>(aggf16, h1f16, b2p, b2,
                                                    (__half*)0, bc, out);
}

// round 17
// speedup vs baseline: 1.0231x; 1.0231x over previous
#include <cuda_runtime.h>
#include <cuda_fp16.h>
#include <cstdint>

#define N_NODES 50000
#define N_EDGES 800000
#define C 128
#define NCLS 40
#define NB_SCAN ((N_NODES + 255) / 256)        // 196
#define PREP_BLOCKS ((N_NODES * C / 4 + 255) / 256)  // 6250
#define EDGE4_BLOCKS ((N_EDGES / 4 + 255) / 256)     // 782
#define EDGE2_BLOCKS ((N_EDGES / 2 + 255) / 256)     // 1563

// ======================= scratch (no allocation allowed) ====================
__device__ __align__(256) float g_deg_inv[N_NODES];
__device__ __align__(256) int   g_deg[N_NODES];    // zero at load; csrfill re-zeroes
__device__ __align__(256) int   g_off[N_NODES + 1];
__device__ __align__(256) int   g_rank[N_EDGES];   // per-edge rank within its dst segment
__device__ __align__(256) int   g_csr_src[N_EDGES];
__device__ __align__(256) int   g_bsum[NB_SCAN];
__device__ __align__(256) int   g_bflag[NB_SCAN];  // zero at load; csrfill re-zeroes
// fp16 activation images
__device__ __align__(256) __half g_x_f16[N_NODES * C];
__device__ __align__(256) __half g_h1_f16[N_NODES * C];
__device__ __align__(256) __half g_agg_f16[N_NODES * C];
// Weight images: plain fp16
__device__ __align__(256) __half g_B1[256 * 128];
__device__ __align__(256) __half g_B2[256 * 128];
__device__ __align__(256) __half g_Wc[128 * 64];
__device__ int g_idx64;

// ======================= helpers =======================
__device__ __forceinline__ uint32_t smem_u32(const void* p) {
    uint32_t a;
    asm("{ .reg .u64 t; cvta.to.shared.u64 t, %1; cvt.u32.u64 %0, t; }"
        : "=r"(a) : "l"(p));
    return a;
}
__device__ __forceinline__ void ldsm_x4(uint32_t& r0, uint32_t& r1,
                                        uint32_t& r2, uint32_t& r3, uint32_t addr) {
    asm volatile("ldmatrix.sync.aligned.m8n8.x4.shared.b16 {%0,%1,%2,%3}, [%4];"
                 : "=r"(r0), "=r"(r1), "=r"(r2), "=r"(r3) : "r"(addr));
}
__device__ __forceinline__ void ldsm_x4_t(uint32_t& r0, uint32_t& r1,
                                          uint32_t& r2, uint32_t& r3, uint32_t addr) {
    asm volatile("ldmatrix.sync.aligned.m8n8.x4.trans.shared.b16 {%0,%1,%2,%3}, [%4];"
                 : "=r"(r0), "=r"(r1), "=r"(r2), "=r"(r3) : "r"(addr));
}
__device__ __forceinline__ void mma_f16(float* c, const uint32_t* a, const uint32_t* b) {
    asm volatile(
        "mma.sync.aligned.m16n8k16.row.col.f32.f16.f16.f32 "
        "{%0,%1,%2,%3}, {%4,%5,%6,%7}, {%8,%9}, {%0,%1,%2,%3};"
        : "+f"(c[0]), "+f"(c[1]), "+f"(c[2]), "+f"(c[3])
        : "r"(a[0]), "r"(a[1]), "r"(a[2]), "r"(a[3]), "r"(b[0]), "r"(b[1]));
}
__device__ __forceinline__ int block_incl_scan(int v, int* wsum /*[8]*/) {
    int lane = threadIdx.x & 31, w = threadIdx.x >> 5;
#pragma unroll
    for (int off = 1; off < 32; off <<= 1) {
        int u = __shfl_up_sync(0xffffffffu, v, off);
        if (lane >= off) v += u;
    }
    if (lane == 31) wsum[w] = v;
    __syncthreads();
    if (w == 0) {
        int s = (lane < 8) ? wsum[lane] : 0;
#pragma unroll
        for (int off = 1; off < 8; off <<= 1) {
            int u = __shfl_up_sync(0xffffffffu, s, off);
            if (lane >= off) s += u;
        }
        if (lane < 8) wsum[lane] = s;
    }
    __syncthreads();
    if (w > 0) v += wsum[w - 1];
    return v;
}

// ====== fused prep + degree histogram (independent work, one grid) ==========
__global__ void __launch_bounds__(256)
prep_deg_kernel(const unsigned int* __restrict__ ei,
                const float* __restrict__ x,
                const float* __restrict__ Wl1, const float* __restrict__ Wr1,
                const float* __restrict__ Wl2, const float* __restrict__ Wr2,
                const float* __restrict__ Wc) {
    const int b = blockIdx.x;
    const int t = threadIdx.x;
    if (b < PREP_BLOCKS) {
        int i = b * 256 + t;
        if (i == 0) {
            int zeros = 0;
            for (int j = 1; j < 128; j += 2) zeros += (ei[j] == 0u);
            g_idx64 = (zeros >= 32) ? 1 : 0;
        }
        if (i < 2 * 256 * 128) {
            int layer = i >> 15;
            int rem = i & 32767;
            int k = rem >> 7;
            int n = rem & 127;
            const float* W = (layer == 0) ? ((k < 128) ? Wl1 : Wr1) : ((k < 128) ? Wl2 : Wr2);
            float v = W[(k & 127) * 128 + n];
            (layer ? g_B2 : g_B1)[k * 128 + n] = __float2half_rn(v);
        } else if (i < 2 * 256 * 128 + 128 * 64) {
            int rem = i - 2 * 256 * 128;
            int k = rem >> 6;
            int n = rem & 63;
            float v = (n < NCLS) ? Wc[k * NCLS + n] : 0.f;
            g_Wc[k * 64 + n] = __float2half_rn(v);
        }
        if (i < N_NODES * C / 4) {
            float4 v = ((const float4*)x)[i];
            __half2 f0 = __floats2half2_rn(v.x, v.y);
            __half2 f1 = __floats2half2_rn(v.z, v.w);
            uint2 f;
            f.x = *(uint32_t*)&f0;
            f.y = *(uint32_t*)&f1;
            ((uint2*)g_x_f16)[i] = f;
        }
    } else {
        // ---- degree histogram + rank recording (self-detects index width) ----
        __shared__ int s64;
        if (t < 32) {
            unsigned z = (ei[2 * t + 1] == 0u) ? 1u : 0u;
            unsigned bal = __ballot_sync(0xffffffffu, z);
            if (t == 0) s64 = (__popc(bal) >= 16) ? 1 : 0;
        }
        __syncthreads();
        const int is64 = s64;
        int i = (b - PREP_BLOCKS) * 256 + t;
        if (i * 4 >= N_EDGES) return;
        int d0, d1, d2, d3;
        if (is64) {
            const longlong2* p = (const longlong2*)((const long long*)ei + N_EDGES);
            longlong2 v0 = p[2 * i], v1 = p[2 * i + 1];
            d0 = (int)v0.x; d1 = (int)v0.y; d2 = (int)v1.x; d3 = (int)v1.y;
        } else {
            int4 v = ((const int4*)((const int*)ei + N_EDGES))[i];
            d0 = v.x; d1 = v.y; d2 = v.z; d3 = v.w;
        }
        int4 r;
        r.x = atomicAdd(&g_deg[d0], 1);
        r.y = atomicAdd(&g_deg[d1], 1);
        r.z = atomicAdd(&g_deg[d2], 1);
        r.w = atomicAdd(&g_deg[d3], 1);
        ((int4*)g_rank)[i] = r;
    }
}

// ---- single-kernel decoupled-lookback scan over g_deg ----
__global__ void __launch_bounds__(256) scan_all_kernel() {
    __shared__ int ws[8];
    __shared__ int blockTotal;
    __shared__ int pre;
    const int t = threadIdx.x, b = blockIdx.x;
    int i = b * 256 + t;
    int d = (i < N_NODES) ? g_deg[i] : 0;
    int inc = block_incl_scan(d, ws);
    if (t == 255) blockTotal = inc;
    if (t == 0) pre = 0;
    __syncthreads();
    if (t == 0) {
        g_bsum[b] = blockTotal;
        __threadfence();
        atomicExch(&g_bflag[b], 1);
    }
    for (int j = t; j < b; j += 256) {
        while (atomicAdd(&g_bflag[j], 0) == 0) {}
        atomicAdd(&pre, atomicAdd(&g_bsum[j], 0));
    }
    __syncthreads();
    if (i < N_NODES) {
        int o = pre + inc - d;
        g_off[i] = o;
        g_deg_inv[i] = (d > 0) ? (1.0f / (float)d) : 0.0f;
    }
    if (b == 0 && t == 0) g_off[N_NODES] = N_EDGES;
}

// CSR fill, 2 edges/thread, NO atomics. Re-zeroes g_deg / g_bflag.
__global__ void csrfill_kernel(const void* __restrict__ ei) {
    int i = blockIdx.x * blockDim.x + threadIdx.x;
    if (i < N_NODES) g_deg[i] = 0;
    if (i < NB_SCAN) g_bflag[i] = 0;
    if (i * 2 >= N_EDGES) return;
    int s0, s1, d0, d1;
    if (g_idx64) {
        longlong2 sv = ((const longlong2*)(const long long*)ei)[i];
        longlong2 dv = ((const longlong2*)((const long long*)ei + N_EDGES))[i];
        s0 = (int)sv.x; s1 = (int)sv.y; d0 = (int)dv.x; d1 = (int)dv.y;
    } else {
        int2 sv = ((const int2*)(const int*)ei)[i];
        int2 dv = ((const int2*)((const int*)ei + N_EDGES))[i];
        s0 = sv.x; s1 = sv.y; d0 = dv.x; d1 = dv.y;
    }
    int2 r = ((const int2*)g_rank)[i];
    g_csr_src[__ldg(&g_off[d0]) + r.x] = s0;
    g_csr_src[__ldg(&g_off[d1]) + r.y] = s1;
}

// ======================= CSR gather-mean (fp16 in, fp16 out) =================
// one warp per node, 4-wide MLP; 4-edge groups accumulated in fp16 (HADD2 tree)
// then flushed to fp32 once per group — cuts cvt/FADD issue work ~36%.
__global__ void __launch_bounds__(256)
gather_kernel(const __half* __restrict__ feat, __half* __restrict__ agg) {
    int node = (blockIdx.x * blockDim.x + threadIdx.x) >> 5;
    int lane = threadIdx.x & 31;
    if (node >= N_NODES) return;
    int e = g_off[node];
    const int end = g_off[node + 1];
    float4 acc = make_float4(0.f, 0.f, 0.f, 0.f);
    for (; e + 4 <= end; e += 4) {
        int i0 = __ldg(&g_csr_src[e]);
        int i1 = __ldg(&g_csr_src[e + 1]);
        int i2 = __ldg(&g_csr_src[e + 2]);
        int i3 = __ldg(&g_csr_src[e + 3]);
        uint2 v0 = *(const uint2*)(feat + (size_t)i0 * C + lane * 4);
        uint2 v1 = *(const uint2*)(feat + (size_t)i1 * C + lane * 4);
        uint2 v2 = *(const uint2*)(feat + (size_t)i2 * C + lane * 4);
        uint2 v3 = *(const uint2*)(feat + (size_t)i3 * C + lane * 4);
        // fp16 pairwise tree (|sum4| << 65504, no overflow risk)
        __half2 sx = __hadd2(__hadd2(*(__half2*)&v0.x, *(__half2*)&v1.x),
                             __hadd2(*(__half2*)&v2.x, *(__half2*)&v3.x));
        __half2 sy = __hadd2(__hadd2(*(__half2*)&v0.y, *(__half2*)&v1.y),
                             __hadd2(*(__half2*)&v2.y, *(__half2*)&v3.y));
        float2 f0 = __half22float2(sx);
        float2 f1 = __half22float2(sy);
        acc.x += f0.x; acc.y += f0.y; acc.z += f1.x; acc.w += f1.y;
    }
    for (; e < end; ++e) {
        int s = __ldg(&g_csr_src[e]);
        uint2 v = *(const uint2*)(feat + (size_t)s * C + lane * 4);
        float2 f0 = __half22float2(*(__half2*)&v.x);
        float2 f1 = __half22float2(*(__half2*)&v.y);
        acc.x += f0.x; acc.y += f0.y; acc.z += f1.x; acc.w += f1.y;
    }
    float s = g_deg_inv[node];
    __half2 o0 = __floats2half2_rn(acc.x * s, acc.y * s);
    __half2 o1 = __floats2half2_rn(acc.z * s, acc.w * s);
    uint2 o;
    o.x = *(uint32_t*)&o0;
    o.y = *(uint32_t*)&o1;
    *(uint2*)(agg + (size_t)node * C + lane * 4) = o;
}

// ======================= HMMA SAGE GEMM (plain fp16) ========================
#define A_STRIDE 72
#define B_STRIDE 136
#define SM_A0 0
#define SM_A1 (128 * A_STRIDE * 2)            // 18432
#define SM_B  (2 * 128 * A_STRIDE * 2)        // 36864
#define SM_TOTAL (2 * 128 * A_STRIDE * 2 + 64 * B_STRIDE * 2)  // 54272 B

template <bool FUSE_CLS>
__global__ void __launch_bounds__(256)
sage_gemm_mma(const __half* __restrict__ agg, const __half* __restrict__ xin,
              const __half* __restrict__ B, const float* __restrict__ bias,
              __half* __restrict__ outf16,
              const float* __restrict__ bc, float* __restrict__ clsout) {
    extern __shared__ unsigned char smem[];
    const uint32_t sbase = smem_u32(smem);
    const int t = threadIdx.x;
    const int wid = t >> 5, lane = t & 31;
    const int warp_m = wid >> 2;
    const int warp_n = wid & 3;
    const int rowBase = blockIdx.x * 128;

    float acc[4][4][4];
#pragma unroll
    for (int i = 0; i < 4; i++)
#pragma unroll
        for (int j = 0; j < 4; j++)
#pragma unroll
            for (int r = 0; r < 4; r++) acc[i][j][r] = 0.f;

    const int a_row = warp_m * 64 + (lane & 15);
    const int a_col = (lane >> 4) * 8;
    const int b_row = (lane & 7) + (lane & 8);
    const int b_col = warp_n * 32 + (lane >> 4) * 8;

    for (int chunk = 0; chunk < 4; ++chunk) {
        const int k0 = chunk * 64;
        const bool isAgg = (chunk < 2);
        const __half* src = isAgg ? agg : xin;
        const int koff = isAgg ? k0 : (k0 - 128);

        // A fill: 128 rows x 64 k fp16 = 1024 uint4
#pragma unroll
        for (int it = 0; it < 4; ++it) {
            int idx = it * 256 + t;
            int row = idx >> 3;
            int q = idx & 7;
            int gm = rowBase + row;
            uint4 v = make_uint4(0u, 0u, 0u, 0u);
            if (gm < N_NODES) v = *(const uint4*)(src + (size_t)gm * C + koff + q * 8);
            uint32_t off = SM_A0 + (uint32_t)(row * A_STRIDE + q * 8) * 2;
            *(uint4*)(smem + off) = v;
        }
        // B fill: 64 k-rows x 128 n = 1024 uint4
#pragma unroll
        for (int it = 0; it < 4; ++it) {
            int idx = it * 256 + t;
            int r = idx >> 4;
            int c8 = (idx & 15) * 8;
            uint4 v = *(const uint4*)(B + (size_t)(k0 + r) * 128 + c8);
            uint32_t off = SM_B + (uint32_t)(r * B_STRIDE + c8) * 2;
            *(uint4*)(smem + off) = v;
        }
        __syncthreads();

#pragma unroll
        for (int ks = 0; ks < 4; ++ks) {
            const int kk = ks * 16;
            uint32_t a[4][4], bh[4][2];
#pragma unroll
            for (int i = 0; i < 4; ++i) {
                uint32_t addr = sbase + SM_A0 +
                    (uint32_t)((a_row + i * 16) * A_STRIDE + kk + a_col) * 2;
                ldsm_x4(a[i][0], a[i][1], a[i][2], a[i][3], addr);
            }
#pragma unroll
            for (int jj = 0; jj < 2; ++jj) {
                uint32_t addr = sbase + SM_B +
                    (uint32_t)((kk + b_row) * B_STRIDE + b_col + jj * 16) * 2;
                ldsm_x4_t(bh[jj * 2][0], bh[jj * 2][1], bh[jj * 2 + 1][0], bh[jj * 2 + 1][1], addr);
            }
#pragma unroll
            for (int i = 0; i < 4; ++i)
#pragma unroll
                for (int j = 0; j < 4; ++j)
                    mma_f16(acc[i][j], a[i], bh[j]);
        }
        __syncthreads();
    }

    const int er = lane >> 2;
    const int ec = (lane & 3) * 2;

    if (!FUSE_CLS) {
        // ---- layer-1 epilogue: bias + relu -> global fp16 ----
#pragma unroll
        for (int i = 0; i < 4; ++i) {
            int gm0 = rowBase + warp_m * 64 + i * 16 + er;
#pragma unroll
            for (int j = 0; j < 4; ++j) {
                int col = warp_n * 32 + j * 8 + ec;
                float b0 = bias[col], b1 = bias[col + 1];
#pragma unroll
                for (int half = 0; half < 2; ++half) {
                    int gm = gm0 + half * 8;
                    if (gm < N_NODES) {
                        float ox = fmaxf(acc[i][j][half * 2 + 0] + b0, 0.f);
                        float oy = fmaxf(acc[i][j][half * 2 + 1] + b1, 0.f);
                        __half2 o2 = __floats2half2_rn(ox, oy);
                        *(uint32_t*)(outf16 + (size_t)gm * C + col) = *(uint32_t*)&o2;
                    }
                }
            }
        }
        return;
    }

    // ---- layer-2 epilogue: bias + relu -> smem h2 tile (A0: 0-63, A1: 64-127)
#pragma unroll
    for (int i = 0; i < 4; ++i) {
        int row0 = warp_m * 64 + i * 16 + er;
#pragma unroll
        for (int j = 0; j < 4; ++j) {
            int col = warp_n * 32 + j * 8 + ec;
            float b0 = bias[col], b1 = bias[col + 1];
            uint32_t region = (col >= 64) ? SM_A1 : SM_A0;
            int colIn = col & 63;
#pragma unroll
            for (int half = 0; half < 2; ++half) {
                int row = row0 + half * 8;
                float ox = fmaxf(acc[i][j][half * 2 + 0] + b0, 0.f);
                float oy = fmaxf(acc[i][j][half * 2 + 1] + b1, 0.f);
                __half2 o2 = __floats2half2_rn(ox, oy);
                *(uint32_t*)(smem + region + (uint32_t)(row * A_STRIDE + colIn) * 2) =
                    *(uint32_t*)&o2;
            }
        }
    }
    __syncthreads();

    // ---- in-CTA classifier: logits = h2_tile @ Wc + bc ----
    float acc2[4][2][4];
#pragma unroll
    for (int i = 0; i < 4; i++)
#pragma unroll
        for (int j = 0; j < 2; j++)
#pragma unroll
            for (int r = 0; r < 4; r++) acc2[i][j][r] = 0.f;

    const int cb_col = warp_n * 16 + (lane >> 4) * 8;

    for (int chunk = 0; chunk < 2; ++chunk) {
        const int k0 = chunk * 64;
        // B fill: Wc 64 k-rows x 64 n = 512 uint4
#pragma unroll
        for (int it = 0; it < 2; ++it) {
            int idx = it * 256 + t;
            int r = idx >> 3;
            int c8 = (idx & 7) * 8;
            uint4 v = *(const uint4*)(g_Wc + (size_t)(k0 + r) * 64 + c8);
            uint32_t off = SM_B + (uint32_t)(r * B_STRIDE + c8) * 2;
            *(uint4*)(smem + off) = v;
        }
        __syncthreads();

        const uint32_t aRegion = chunk ? SM_A1 : SM_A0;
#pragma unroll
        for (int ks = 0; ks < 4; ++ks) {
            const int kk = ks * 16;
            uint32_t a[4][4], bh[2][2];
#pragma unroll
            for (int i = 0; i < 4; ++i) {
                uint32_t addr = sbase + aRegion +
                    (uint32_t)((a_row + i * 16) * A_STRIDE + kk + a_col) * 2;
                ldsm_x4(a[i][0], a[i][1], a[i][2], a[i][3], addr);
            }
            {
                uint32_t addr = sbase + SM_B +
                    (uint32_t)((kk + b_row) * B_STRIDE + cb_col) * 2;
                ldsm_x4_t(bh[0][0], bh[0][1], bh[1][0], bh[1][1], addr);
            }
#pragma unroll
            for (int i = 0; i < 4; ++i)
#pragma unroll
                for (int j = 0; j < 2; ++j)
                    mma_f16(acc2[i][j], a[i], bh[j]);
        }
        __syncthreads();
    }

#pragma unroll
    for (int i = 0; i < 4; ++i) {
        int gm0 = rowBase + warp_m * 64 + i * 16 + er;
#pragma unroll
        for (int j = 0; j < 2; ++j) {
            int col = warp_n * 16 + j * 8 + ec;
            if (col >= NCLS) continue;
            float b0 = bc[col], b1 = bc[col + 1];
#pragma unroll
            for (int half = 0; half < 2; ++half) {
                int gm = gm0 + half * 8;
                if (gm < N_NODES) {
                    float2 o;
                    o.x = acc2[i][j][half * 2 + 0] + b0;
                    o.y = acc2[i][j][half * 2 + 1] + b1;
                    *(float2*)(clsout + (size_t)gm * NCLS + col) = o;
                }
            }
        }
    }
}

// ======================= launch =======================
extern "C" void kernel_launch(void* const* d_in, const int* in_sizes, int n_in,
                              void* d_out, int out_size) {
    (void)in_sizes; (void)n_in; (void)out_size;
    const float* x   = (const float*)d_in[0];
    const void*  ei  = d_in[1];
    const float* Wl1 = (const float*)d_in[2];
    const float* Wr1 = (const float*)d_in[3];
    const float* b1  = (const float*)d_in[4];
    const float* Wl2 = (const float*)d_in[5];
    const float* Wr2 = (const float*)d_in[6];
    const float* b2  = (const float*)d_in[7];
    const float* Wc  = (const float*)d_in[8];
    const float* bc  = (const float*)d_in[9];
    float* out = (float*)d_out;

    __half *xf16, *h1f16, *aggf16;
    cudaGetSymbolAddress((void**)&xf16, g_x_f16);
    cudaGetSymbolAddress((void**)&h1f16, g_h1_f16);
    cudaGetSymbolAddress((void**)&aggf16, g_agg_f16);
    __half *b1p, *b2p;
    cudaGetSymbolAddress((void**)&b1p, g_B1);
    cudaGetSymbolAddress((void**)&b2p, g_B2);

    cudaFuncSetAttribute(sage_gemm_mma<false>, cudaFuncAttributeMaxDynamicSharedMemorySize, SM_TOTAL);
    cudaFuncSetAttribute(sage_gemm_mma<true>, cudaFuncAttributeMaxDynamicSharedMemorySize, SM_TOTAL);

    const int nBlocks = (N_NODES + 127) / 128;            // 391
    const int gatherBlocks = (N_NODES * 32 + 255) / 256;  // 6250

    // fused prep + degree histogram (records per-edge ranks for atomic-free fill)
    prep_deg_kernel<<<PREP_BLOCKS + EDGE4_BLOCKS, 256>>>(
        (const unsigned int*)ei, x, Wl1, Wr1, Wl2, Wr2, Wc);

    // CSR build: single-kernel decoupled-lookback scan, then atomic-free fill
    scan_all_kernel<<<NB_SCAN, 256>>>();
    csrfill_kernel<<<EDGE2_BLOCKS, 256>>>(ei);

    // layer 1
    gather_kernel<<<gatherBlocks, 256>>>(xf16, aggf16);
    sage_gemm_mma<false><<<nBlocks, 256, SM_TOTAL>>>(aggf16, xf16, b1p, b1,
                                                     h1f16, (const float*)0, (float*)0);

    // layer 2 + fused classifier
    gather_kernel<<<gatherBlocks, 256>>>(h1f16, aggf16);
    sage_gemm_mma<true><<<nBlocks, 256, SM_TOTAL>>>(aggf16, h1f16, b2p, b2,
                                                    (__half*)0, bc, out);
}